// round 1
// baseline (speedup 1.0000x reference)
#include <cuda_runtime.h>
#include <math.h>

#define B_   8
#define S_   2048
#define DIN  1024
#define DK   64
#define MTOT (B_ * S_)           // 16384 rows

// Scratch for projected Q, K, V  (4 MB each)
__device__ float g_Q[MTOT * DK];
__device__ float g_K[MTOT * DK];
__device__ float g_V[MTOT * DK];

// ---------------------------------------------------------------------------
// Fused QKV projection: [16384 x 1024] @ [1024 x 64] x3, N fused to 192.
// Block: 256 threads (16x16), 64 rows per block, 4x12 micro-tile per thread.
// ---------------------------------------------------------------------------
__global__ __launch_bounds__(256) void qkv_kernel(
    const float* __restrict__ X,
    const float* __restrict__ Wq,
    const float* __restrict__ Wk,
    const float* __restrict__ Wv)
{
    __shared__ float Xs[64][17];     // pad 17: avoids bank clash on broadcast rows
    __shared__ float Ws[16][192];    // [kk][n], n: 0..63 Q | 64..127 K | 128..191 V

    const int t  = threadIdx.x;
    const int ty = t >> 4;           // 0..15 -> 4 rows each
    const int tx = t & 15;           // 0..15 -> 4 cols per matrix
    const int m0 = blockIdx.x * 64;

    float acc[4][12];
#pragma unroll
    for (int i = 0; i < 4; i++)
#pragma unroll
        for (int j = 0; j < 12; j++) acc[i][j] = 0.0f;

    for (int kb = 0; kb < DIN / 16; kb++) {
        __syncthreads();
        // Load X tile [64 x 16]
        {
            const int r = t >> 2, seg = t & 3;
            float4 x4 = *(const float4*)&X[(size_t)(m0 + r) * DIN + kb * 16 + seg * 4];
            Xs[r][seg * 4 + 0] = x4.x;
            Xs[r][seg * 4 + 1] = x4.y;
            Xs[r][seg * 4 + 2] = x4.z;
            Xs[r][seg * 4 + 3] = x4.w;
        }
        // Load W tiles [16 x 64] x3
        {
            const int r = t >> 4;
            const int c = (t & 15) * 4;
            const int gk = kb * 16 + r;
            *(float4*)&Ws[r][c]       = *(const float4*)&Wq[gk * 64 + c];
            *(float4*)&Ws[r][64 + c]  = *(const float4*)&Wk[gk * 64 + c];
            *(float4*)&Ws[r][128 + c] = *(const float4*)&Wv[gk * 64 + c];
        }
        __syncthreads();

#pragma unroll
        for (int kk = 0; kk < 16; kk++) {
            float x[4];
#pragma unroll
            for (int i = 0; i < 4; i++) x[i] = Xs[ty * 4 + i][kk];
            float w[12];
            *(float4*)&w[0] = *(const float4*)&Ws[kk][tx * 4];
            *(float4*)&w[4] = *(const float4*)&Ws[kk][64 + tx * 4];
            *(float4*)&w[8] = *(const float4*)&Ws[kk][128 + tx * 4];
#pragma unroll
            for (int i = 0; i < 4; i++)
#pragma unroll
                for (int j = 0; j < 12; j++) acc[i][j] += x[i] * w[j];
        }
    }

#pragma unroll
    for (int i = 0; i < 4; i++) {
        const size_t row = (size_t)(m0 + ty * 4 + i);
        *(float4*)&g_Q[row * DK + tx * 4] = make_float4(acc[i][0], acc[i][1], acc[i][2], acc[i][3]);
        *(float4*)&g_K[row * DK + tx * 4] = make_float4(acc[i][4], acc[i][5], acc[i][6], acc[i][7]);
        *(float4*)&g_V[row * DK + tx * 4] = make_float4(acc[i][8], acc[i][9], acc[i][10], acc[i][11]);
    }
}

// ---------------------------------------------------------------------------
// Flash attention with causal mask. Grid: (S/64 q-tiles, B). 256 threads.
// Thread (ty,tx): 4 query rows (ty*4..), 4 score cols / 4 output dims (tx*4..).
// K stored transposed in smem -> all hot-loop smem accesses conflict-free.
// smem: Qs + Kt + Vs + Ps, each 64x64 f32 = 64 KB total (dynamic).
// ---------------------------------------------------------------------------
__global__ __launch_bounds__(256) void attn_kernel(float* __restrict__ out)
{
    extern __shared__ float sm[];
    float* Qs = sm;                 // [64][64]  row-major (q row, k dim)
    float* Kt = sm + 64 * 64;       // [64][64]  TRANSPOSED: (k dim, kv row)
    float* Vs = sm + 2 * 64 * 64;   // [64][64]  (kv row, out dim)
    float* Ps = sm + 3 * 64 * 64;   // [64][64]  probs (q row, kv row)

    const int qt = blockIdx.x;
    const int b  = blockIdx.y;
    const int t  = threadIdx.x;
    const int ty = t >> 4;          // 0..15
    const int tx = t & 15;          // 0..15
    const int q0 = qt * 64;
    const size_t base = (size_t)b * S_ * DK;

    // Load Q tile (once)
    {
        const int r = t >> 2, seg = t & 3;
#pragma unroll
        for (int u = 0; u < 4; u++) {
            const int c = seg * 16 + u * 4;
            *(float4*)&Qs[r * 64 + c] =
                *(const float4*)&g_Q[base + (size_t)(q0 + r) * DK + c];
        }
    }

    float m[4], l[4], O[4][4];
#pragma unroll
    for (int i = 0; i < 4; i++) {
        m[i] = -INFINITY; l[i] = 0.0f;
#pragma unroll
        for (int u = 0; u < 4; u++) O[i][u] = 0.0f;
    }

    for (int kt = 0; kt <= qt; kt++) {
        __syncthreads();   // previous AV done before overwriting Kt/Vs
        // Load K (transposed) and V tiles
        {
            const int r = t >> 2, seg = t & 3;
            const size_t grow = base + (size_t)(kt * 64 + r) * DK;
#pragma unroll
            for (int u = 0; u < 4; u++) {
                const int c = seg * 16 + u * 4;
                float4 k4 = *(const float4*)&g_K[grow + c];
                Kt[(c + 0) * 64 + r] = k4.x;
                Kt[(c + 1) * 64 + r] = k4.y;
                Kt[(c + 2) * 64 + r] = k4.z;
                Kt[(c + 3) * 64 + r] = k4.w;
                *(float4*)&Vs[r * 64 + c] = *(const float4*)&g_V[grow + c];
            }
        }
        __syncthreads();

        // Scores: s[i][j] = Q[row_i] . K[col_j]
        float s[4][4];
#pragma unroll
        for (int i = 0; i < 4; i++)
#pragma unroll
            for (int j = 0; j < 4; j++) s[i][j] = 0.0f;

        for (int kc = 0; kc < 64; kc += 4) {
            float4 qf[4];
#pragma unroll
            for (int i = 0; i < 4; i++)
                qf[i] = *(const float4*)&Qs[(ty * 4 + i) * 64 + kc];
#define SCORE_STEP(KK, COMP)                                               \
            {                                                              \
                float4 kf = *(const float4*)&Kt[(kc + KK) * 64 + tx * 4];  \
                _Pragma("unroll")                                          \
                for (int i = 0; i < 4; i++) {                              \
                    float qv = qf[i].COMP;                                 \
                    s[i][0] += qv * kf.x;                                  \
                    s[i][1] += qv * kf.y;                                  \
                    s[i][2] += qv * kf.z;                                  \
                    s[i][3] += qv * kf.w;                                  \
                }                                                          \
            }
            SCORE_STEP(0, x)
            SCORE_STEP(1, y)
            SCORE_STEP(2, z)
            SCORE_STEP(3, w)
#undef SCORE_STEP
        }

        // Scale + causal mask (only the diagonal tile needs masking)
        const float sc_qk = 0.125f;  // 1/sqrt(64)
#pragma unroll
        for (int i = 0; i < 4; i++)
#pragma unroll
            for (int j = 0; j < 4; j++) s[i][j] *= sc_qk;
        if (kt == qt) {
#pragma unroll
            for (int i = 0; i < 4; i++)
#pragma unroll
                for (int j = 0; j < 4; j++)
                    if (tx * 4 + j > ty * 4 + i) s[i][j] = -INFINITY;
        }

        // Online softmax (row reduction across the 16 tx lanes)
#pragma unroll
        for (int i = 0; i < 4; i++) {
            float tm = fmaxf(fmaxf(s[i][0], s[i][1]), fmaxf(s[i][2], s[i][3]));
#pragma unroll
            for (int o = 1; o < 16; o <<= 1)
                tm = fmaxf(tm, __shfl_xor_sync(0xffffffffu, tm, o));
            const float mn  = fmaxf(m[i], tm);
            const float scl = __expf(m[i] - mn);
            const float p0 = __expf(s[i][0] - mn);
            const float p1 = __expf(s[i][1] - mn);
            const float p2 = __expf(s[i][2] - mn);
            const float p3 = __expf(s[i][3] - mn);
            float rs = p0 + p1 + p2 + p3;
#pragma unroll
            for (int o = 1; o < 16; o <<= 1)
                rs += __shfl_xor_sync(0xffffffffu, rs, o);
            l[i] = l[i] * scl + rs;
            m[i] = mn;
#pragma unroll
            for (int u = 0; u < 4; u++) O[i][u] *= scl;
            *(float4*)&Ps[(ty * 4 + i) * 64 + tx * 4] = make_float4(p0, p1, p2, p3);
        }
        __syncthreads();   // Ps fully written before AV reads other lanes' cols

        // AV: O[i][u] += sum_j P[row_i][j] * V[j][dim_u]
        for (int j0 = 0; j0 < 64; j0 += 4) {
            float4 v0 = *(const float4*)&Vs[(j0 + 0) * 64 + tx * 4];
            float4 v1 = *(const float4*)&Vs[(j0 + 1) * 64 + tx * 4];
            float4 v2 = *(const float4*)&Vs[(j0 + 2) * 64 + tx * 4];
            float4 v3 = *(const float4*)&Vs[(j0 + 3) * 64 + tx * 4];
#pragma unroll
            for (int i = 0; i < 4; i++) {
                float4 p = *(const float4*)&Ps[(ty * 4 + i) * 64 + j0];
                O[i][0] += p.x * v0.x + p.y * v1.x + p.z * v2.x + p.w * v3.x;
                O[i][1] += p.x * v0.y + p.y * v1.y + p.z * v2.y + p.w * v3.y;
                O[i][2] += p.x * v0.z + p.y * v1.z + p.z * v2.z + p.w * v3.z;
                O[i][3] += p.x * v0.w + p.y * v1.w + p.z * v2.w + p.w * v3.w;
            }
        }
    }

    // Normalize + store
#pragma unroll
    for (int i = 0; i < 4; i++) {
        const float inv = 1.0f / l[i];
        const size_t row = base + (size_t)(q0 + ty * 4 + i) * DK;
        *(float4*)&out[row + tx * 4] =
            make_float4(O[i][0] * inv, O[i][1] * inv, O[i][2] * inv, O[i][3] * inv);
    }
}

// ---------------------------------------------------------------------------
extern "C" void kernel_launch(void* const* d_in, const int* in_sizes, int n_in,
                              void* d_out, int out_size)
{
    const float* X  = (const float*)d_in[0];
    const float* Wq = (const float*)d_in[1];
    const float* Wk = (const float*)d_in[2];
    const float* Wv = (const float*)d_in[3];
    float* out = (float*)d_out;

    qkv_kernel<<<MTOT / 64, 256>>>(X, Wq, Wk, Wv);

    const int attn_smem = 4 * 64 * 64 * (int)sizeof(float);  // 64 KB
    cudaFuncSetAttribute(attn_kernel,
                         cudaFuncAttributeMaxDynamicSharedMemorySize, attn_smem);
    attn_kernel<<<dim3(S_ / 64, B_), 256, attn_smem>>>(out);
}